// round 7
// baseline (speedup 1.0000x reference)
#include <cuda_runtime.h>
#include <cuda_bf16.h>

// Fused Swin window attention, fp32 + packed f32x2 FMA. One CTA per 8x8 window.
// B=4, H=W=256, C=192, WS=8, NH=6, HD=32.
// R7: conflict-aware transpose lane mapping (2-way, was 16/32-way), padded Ps
// (stride 68, softmax stores 4-way), 4m x 8n weight GEMM tiles (1.5 B/MAC),
// rpb table overlaid on weight buffer 0, double-buffered one-barrier pipeline.
//
// smem (floats):
//   Xs [192][68]  X^T (k-major, padded); reused as attn-out^T for proj
//   Qs [6][32][64], Ks [6][32][64]  d-major
//   Vs [6][64][32] token-major
//   Ps [64][68]   softmax probs (attention) / weight buf1 (GEMM phases)
//   Bt [24][132]  weight buf0 (GEMM phases) / rpb table (attention phase)

#define XS_STRIDE 68
#define PS_STRIDE 68
#define SM_X   0
#define SM_Q   13056
#define SM_K   25344
#define SM_V   37632
#define SM_P   49920
#define SM_B   54272
#define SM_FLOATS 57536
#define SMEM_BYTES (SM_FLOATS * 4)

#define KT 24          // K rows per weight tile
#define BW_STRIDE 132  // wide tile (128 cols + 4 pad)
#define BN_STRIDE 68   // narrow tile (64 cols + 4 pad)

typedef unsigned long long u64;

__device__ __forceinline__ u64 bc2(float v) {
    u64 r;
    asm("mov.b64 %0, {%1, %1};" : "=l"(r) : "r"(__float_as_uint(v)));
    return r;
}
__device__ __forceinline__ void fma2(u64& d, u64 a, u64 b) {
    asm("fma.rn.f32x2 %0, %1, %2, %0;" : "+l"(d) : "l"(a), "l"(b));
}
__device__ __forceinline__ u64 mul2(u64 a, u64 b) {
    u64 r;
    asm("mul.rn.f32x2 %0, %1, %2;" : "=l"(r) : "l"(a), "l"(b));
    return r;
}
__device__ __forceinline__ float2 unpk(u64 a) {
    unsigned lo, hi;
    asm("mov.b64 {%0, %1}, %2;" : "=r"(lo), "=r"(hi) : "l"(a));
    return make_float2(__uint_as_float(lo), __uint_as_float(hi));
}

__global__ __launch_bounds__(256, 1)
void win_attn_kernel(const float* __restrict__ x,
                     const float* __restrict__ qkv_w,
                     const float* __restrict__ proj_w,
                     const float* __restrict__ proj_b,
                     const float* __restrict__ rpb,
                     float* __restrict__ out)
{
    extern __shared__ float sm[];
    float* Xs = sm + SM_X;
    float* Qs = sm + SM_Q;
    float* Ks = sm + SM_K;
    float* Vs = sm + SM_V;
    float* Ps = sm + SM_P;
    float* Rs = sm + SM_B;       // rpb table, attention phase only
    float* wb[2];
    wb[0] = sm + SM_B;           // weight buf0 (GEMM phases)
    wb[1] = sm + SM_P;           // weight buf1 aliases Ps

    const int tid = threadIdx.x;
    const int i = tid >> 4;      // m-group: rows 4i..4i+3
    const int j = tid & 15;      // n-group
    const int blk = blockIdx.x;
    const int b  = blk >> 10;
    const int wy = (blk >> 5) & 31;
    const int wx = blk & 31;
    const int base = ((b * 256 + wy * 8) * 256 + wx * 8) * 192;

    // ---- load X window transposed into Xs[k][m] ----
    // lane l -> (dm = l>>2, dc = l&3); warp w owns window-row w.
    // store bank = (16*(dc&1) + dm + ...) -> 2-way conflicts only.
    {
        const int dm = (tid >> 2) & 7;
        const int dc = tid & 3;
        const int w  = tid >> 5;
        const int m  = w * 8 + dm;
        const float* src = x + base + (w * 256 + dm) * 192 + dc * 4;
        float* dstb = Xs + dc * 4 * XS_STRIDE + m;
        #pragma unroll
        for (int p = 0; p < 12; p++) {
            float4 v = *(const float4*)(src + p * 16);
            float* dst = dstb + p * 16 * XS_STRIDE;
            dst[0]             = v.x;
            dst[XS_STRIDE]     = v.y;
            dst[2 * XS_STRIDE] = v.z;
            dst[3 * XS_STRIDE] = v.w;
        }
    }

    const u64 sc2 = bc2(0.17677669529663687f);  // 32^-0.5 packed

    // staging coords: wide tile = 24k x 128n = 768 float4 (3/thread)
    int wnW[3], wkW[3];
    #pragma unroll
    for (int p = 0; p < 3; p++) {
        int idx = p * 256 + tid;
        wnW[p] = idx / 6;        // 0..127
        wkW[p] = idx % 6;        // 0..5 (k/4)
    }
    // narrow tile = 24k x 64n = 384 float4 (threads 0..255 one, 0..127 two)
    int wnN[2], wkN[2];
    wnN[0] = tid / 6;         wkN[0] = tid % 6;
    wnN[1] = (256 + tid) / 6; wkN[1] = (256 + tid) % 6;

    float4 wr[3];
    // prologue: QKV wide tile 0 (chunk 0, koff 0)
    #pragma unroll
    for (int p = 0; p < 3; p++)
        wr[p] = *(const float4*)(qkv_w + wnW[p] * 192 + wkW[p] * 4);
    #pragma unroll
    for (int p = 0; p < 3; p++) {
        float* dst = wb[0] + wkW[p] * 4 * BW_STRIDE + wnW[p];
        dst[0]             = wr[p].x;
        dst[BW_STRIDE]     = wr[p].y;
        dst[2 * BW_STRIDE] = wr[p].z;
        dst[3 * BW_STRIDE] = wr[p].w;
    }
    __syncthreads();   // tile 0 staged; also orders Xs stores

    // ---- GEMM1 wide: QKV cols 0..511 (4 chunks x 128) x 8 K-tiles ----
    u64 acc[2][8] = {};
    for (int t = 0; t < 32; t++) {
        if (t + 1 < 32) {
            const int nn = ((t + 1) >> 3) * 128;
            const int nk = ((t + 1) & 7) * KT;
            #pragma unroll
            for (int p = 0; p < 3; p++)
                wr[p] = *(const float4*)(qkv_w + (nn + wnW[p]) * 192 + nk + wkW[p] * 4);
        }
        const float* bt = wb[t & 1];
        const float* xk = Xs + ((t & 7) * KT) * XS_STRIDE;
        #pragma unroll 4
        for (int k = 0; k < KT; k++) {
            ulonglong2 a2 = *(const ulonglong2*)(xk + k * XS_STRIDE + i * 4);
            const float* br = bt + k * BW_STRIDE + j * 8;
            float4 b0 = *(const float4*)br;
            float4 b1 = *(const float4*)(br + 4);
            u64 q0 = bc2(b0.x), q1 = bc2(b0.y), q2 = bc2(b0.z), q3 = bc2(b0.w);
            fma2(acc[0][0], a2.x, q0); fma2(acc[1][0], a2.y, q0);
            fma2(acc[0][1], a2.x, q1); fma2(acc[1][1], a2.y, q1);
            fma2(acc[0][2], a2.x, q2); fma2(acc[1][2], a2.y, q2);
            fma2(acc[0][3], a2.x, q3); fma2(acc[1][3], a2.y, q3);
            u64 q4 = bc2(b1.x), q5 = bc2(b1.y), q6 = bc2(b1.z), q7 = bc2(b1.w);
            fma2(acc[0][4], a2.x, q4); fma2(acc[1][4], a2.y, q4);
            fma2(acc[0][5], a2.x, q5); fma2(acc[1][5], a2.y, q5);
            fma2(acc[0][6], a2.x, q6); fma2(acc[1][6], a2.y, q6);
            fma2(acc[0][7], a2.x, q7); fma2(acc[1][7], a2.y, q7);
        }
        if (t + 1 < 32) {
            float* bn = wb[(t + 1) & 1];
            #pragma unroll
            for (int p = 0; p < 3; p++) {
                float* dst = bn + wkW[p] * 4 * BW_STRIDE + wnW[p];
                dst[0]             = wr[p].x;
                dst[BW_STRIDE]     = wr[p].y;
                dst[2 * BW_STRIDE] = wr[p].z;
                dst[3 * BW_STRIDE] = wr[p].w;
            }
        }
        if ((t & 7) == 7) {
            // chunk epilogue: this thread's 8 cols live in one head (d0 in {0,8,16,24})
            const int col0 = (t >> 3) * 128 + j * 8;
            const int s    = col0 / 192;
            const int rem  = col0 - s * 192;
            const int h    = rem >> 5;
            const int d0   = rem & 31;
            if (s == 0) {
                float* qp = Qs + h * 2048 + d0 * 64 + i * 4;
                #pragma unroll
                for (int c = 0; c < 8; c++) {
                    ulonglong2 cv;
                    cv.x = mul2(acc[0][c], sc2);
                    cv.y = mul2(acc[1][c], sc2);
                    *(ulonglong2*)(qp + c * 64) = cv;
                }
            } else if (s == 1) {
                float* kp = Ks + h * 2048 + d0 * 64 + i * 4;
                #pragma unroll
                for (int c = 0; c < 8; c++) {
                    ulonglong2 cv;
                    cv.x = acc[0][c];
                    cv.y = acc[1][c];
                    *(ulonglong2*)(kp + c * 64) = cv;
                }
            } else {
                float* vh = Vs + h * 2048;
                float2 L[8], Hh[8];
                #pragma unroll
                for (int c = 0; c < 8; c++) { L[c] = unpk(acc[0][c]); Hh[c] = unpk(acc[1][c]); }
                float* r0 = vh + (i * 4 + 0) * 32 + d0;
                float* r1 = vh + (i * 4 + 1) * 32 + d0;
                float* r2 = vh + (i * 4 + 2) * 32 + d0;
                float* r3 = vh + (i * 4 + 3) * 32 + d0;
                *(float4*)(r0)     = make_float4(L[0].x, L[1].x, L[2].x, L[3].x);
                *(float4*)(r0 + 4) = make_float4(L[4].x, L[5].x, L[6].x, L[7].x);
                *(float4*)(r1)     = make_float4(L[0].y, L[1].y, L[2].y, L[3].y);
                *(float4*)(r1 + 4) = make_float4(L[4].y, L[5].y, L[6].y, L[7].y);
                *(float4*)(r2)     = make_float4(Hh[0].x, Hh[1].x, Hh[2].x, Hh[3].x);
                *(float4*)(r2 + 4) = make_float4(Hh[4].x, Hh[5].x, Hh[6].x, Hh[7].x);
                *(float4*)(r3)     = make_float4(Hh[0].y, Hh[1].y, Hh[2].y, Hh[3].y);
                *(float4*)(r3 + 4) = make_float4(Hh[4].y, Hh[5].y, Hh[6].y, Hh[7].y);
            }
            #pragma unroll
            for (int c = 0; c < 8; c++) { acc[0][c] = 0ull; acc[1][c] = 0ull; }
        }
        __syncthreads();
    }

    // ---- GEMM1 narrow: QKV cols 512..575 (V heads 4,5) ----
    float4 wrN[2];
    wrN[0] = *(const float4*)(qkv_w + (512 + wnN[0]) * 192 + wkN[0] * 4);
    if (tid < 128)
        wrN[1] = *(const float4*)(qkv_w + (512 + wnN[1]) * 192 + wkN[1] * 4);
    {
        float* dst = wb[0] + wkN[0] * 4 * BN_STRIDE + wnN[0];
        dst[0] = wrN[0].x; dst[BN_STRIDE] = wrN[0].y;
        dst[2 * BN_STRIDE] = wrN[0].z; dst[3 * BN_STRIDE] = wrN[0].w;
        if (tid < 128) {
            float* d2 = wb[0] + wkN[1] * 4 * BN_STRIDE + wnN[1];
            d2[0] = wrN[1].x; d2[BN_STRIDE] = wrN[1].y;
            d2[2 * BN_STRIDE] = wrN[1].z; d2[3 * BN_STRIDE] = wrN[1].w;
        }
    }
    __syncthreads();
    {
        u64 an[2][4] = {};
        for (int t = 0; t < 8; t++) {
            if (t + 1 < 8) {
                const int nk = (t + 1) * KT;
                wrN[0] = *(const float4*)(qkv_w + (512 + wnN[0]) * 192 + nk + wkN[0] * 4);
                if (tid < 128)
                    wrN[1] = *(const float4*)(qkv_w + (512 + wnN[1]) * 192 + nk + wkN[1] * 4);
            }
            const float* bt = wb[t & 1];
            const float* xk = Xs + (t * KT) * XS_STRIDE;
            #pragma unroll 4
            for (int k = 0; k < KT; k++) {
                ulonglong2 a2 = *(const ulonglong2*)(xk + k * XS_STRIDE + i * 4);
                float4 b0 = *(const float4*)(bt + k * BN_STRIDE + j * 4);
                u64 q0 = bc2(b0.x), q1 = bc2(b0.y), q2 = bc2(b0.z), q3 = bc2(b0.w);
                fma2(an[0][0], a2.x, q0); fma2(an[1][0], a2.y, q0);
                fma2(an[0][1], a2.x, q1); fma2(an[1][1], a2.y, q1);
                fma2(an[0][2], a2.x, q2); fma2(an[1][2], a2.y, q2);
                fma2(an[0][3], a2.x, q3); fma2(an[1][3], a2.y, q3);
            }
            if (t + 1 < 8) {
                float* bn = wb[(t + 1) & 1];
                float* dst = bn + wkN[0] * 4 * BN_STRIDE + wnN[0];
                dst[0] = wrN[0].x; dst[BN_STRIDE] = wrN[0].y;
                dst[2 * BN_STRIDE] = wrN[0].z; dst[3 * BN_STRIDE] = wrN[0].w;
                if (tid < 128) {
                    float* d2 = bn + wkN[1] * 4 * BN_STRIDE + wnN[1];
                    d2[0] = wrN[1].x; d2[BN_STRIDE] = wrN[1].y;
                    d2[2 * BN_STRIDE] = wrN[1].z; d2[3 * BN_STRIDE] = wrN[1].w;
                }
                __syncthreads();
            }
        }
        // epilogue: all V (s==2), rem = 128 + j*4
        const int rem = 128 + j * 4;
        const int h = rem >> 5, d0 = rem & 31;
        float* vh = Vs + h * 2048;
        float2 L[4], Hh[4];
        #pragma unroll
        for (int c = 0; c < 4; c++) { L[c] = unpk(an[0][c]); Hh[c] = unpk(an[1][c]); }
        *(float4*)(vh + (i * 4 + 0) * 32 + d0) = make_float4(L[0].x, L[1].x, L[2].x, L[3].x);
        *(float4*)(vh + (i * 4 + 1) * 32 + d0) = make_float4(L[0].y, L[1].y, L[2].y, L[3].y);
        *(float4*)(vh + (i * 4 + 2) * 32 + d0) = make_float4(Hh[0].x, Hh[1].x, Hh[2].x, Hh[3].x);
        *(float4*)(vh + (i * 4 + 3) * 32 + d0) = make_float4(Hh[0].y, Hh[1].y, Hh[2].y, Hh[3].y);
    }

    // ---- stage rpb into Rs (overlays weight buf0; safe: buf0 dead) ----
    for (int t = tid; t < 1350; t += 256) Rs[t] = rpb[t];
    // prefetch proj wide tile 0 (held in regs through attention)
    #pragma unroll
    for (int p = 0; p < 3; p++)
        wr[p] = *(const float4*)(proj_w + wnW[p] * 192 + wkW[p] * 4);
    __syncthreads();   // QKV complete + Rs ready

    // ---- rpb offsets for this thread's S tile ----
    int ridx[4][4];
    #pragma unroll
    for (int di = 0; di < 4; di++) {
        int m = i * 4 + di, qr = m >> 3, qc = m & 7;
        #pragma unroll
        for (int dj = 0; dj < 4; dj++) {
            int n = j * 4 + dj, kr = n >> 3, kc = n & 7;
            ridx[di][dj] = ((qr - kr + 7) * 15 + (qc - kc + 7)) * 6;
        }
    }

    // ---- attention per head ----
    for (int h = 0; h < 6; h++) {
        const float* qh = Qs + h * 2048;
        const float* kh = Ks + h * 2048;
        u64 s2[4][2] = {};
        #pragma unroll 4
        for (int d = 0; d < 32; d++) {
            float4 a      = *(const float4*)(qh + d * 64 + i * 4);
            ulonglong2 b2 = *(const ulonglong2*)(kh + d * 64 + j * 4);
            u64 a0 = bc2(a.x), a1 = bc2(a.y), a2b = bc2(a.z), a3 = bc2(a.w);
            fma2(s2[0][0], a0, b2.x);  fma2(s2[0][1], a0, b2.y);
            fma2(s2[1][0], a1, b2.x);  fma2(s2[1][1], a1, b2.y);
            fma2(s2[2][0], a2b, b2.x); fma2(s2[2][1], a2b, b2.y);
            fma2(s2[3][0], a3, b2.x);  fma2(s2[3][1], a3, b2.y);
        }
        float p[4][4];
        #pragma unroll
        for (int di = 0; di < 4; di++) {
            float2 s01 = unpk(s2[di][0]), s23 = unpk(s2[di][1]);
            float sv0 = s01.x + Rs[ridx[di][0] + h];
            float sv1 = s01.y + Rs[ridx[di][1] + h];
            float sv2 = s23.x + Rs[ridx[di][2] + h];
            float sv3 = s23.y + Rs[ridx[di][3] + h];
            float mx = fmaxf(fmaxf(sv0, sv1), fmaxf(sv2, sv3));
            mx = fmaxf(mx, __shfl_xor_sync(0xffffffffu, mx, 8));
            mx = fmaxf(mx, __shfl_xor_sync(0xffffffffu, mx, 4));
            mx = fmaxf(mx, __shfl_xor_sync(0xffffffffu, mx, 2));
            mx = fmaxf(mx, __shfl_xor_sync(0xffffffffu, mx, 1));
            float e0 = __expf(sv0 - mx), e1 = __expf(sv1 - mx);
            float e2 = __expf(sv2 - mx), e3 = __expf(sv3 - mx);
            float sum = (e0 + e1) + (e2 + e3);
            sum += __shfl_xor_sync(0xffffffffu, sum, 8);
            sum += __shfl_xor_sync(0xffffffffu, sum, 4);
            sum += __shfl_xor_sync(0xffffffffu, sum, 2);
            sum += __shfl_xor_sync(0xffffffffu, sum, 1);
            float inv = __frcp_rn(sum);
            p[di][0] = e0 * inv; p[di][1] = e1 * inv;
            p[di][2] = e2 * inv; p[di][3] = e3 * inv;
        }
        __syncthreads();   // prior Ps readers done
        #pragma unroll
        for (int dj = 0; dj < 4; dj++)
            *(float4*)(Ps + (j * 4 + dj) * PS_STRIDE + i * 4) =
                make_float4(p[0][dj], p[1][dj], p[2][dj], p[3][dj]);
        __syncthreads();   // Ps ready

        const float* vh = Vs + h * 2048;
        u64 o2[2][2] = {};
        #pragma unroll 4
        for (int kk = 0; kk < 64; kk++) {
            ulonglong2 a2 = *(const ulonglong2*)(Ps + kk * PS_STRIDE + i * 4);
            float2 bv = *(const float2*)(vh + kk * 32 + j * 2);
            u64 b0 = bc2(bv.x), b1 = bc2(bv.y);
            fma2(o2[0][0], a2.x, b0); fma2(o2[0][1], a2.x, b1);
            fma2(o2[1][0], a2.y, b0); fma2(o2[1][1], a2.y, b1);
        }
        float* ot = Xs + (h * 32 + j * 2) * XS_STRIDE + i * 4;
        ulonglong2 c0, c1;
        c0.x = o2[0][0]; c0.y = o2[1][0];
        c1.x = o2[0][1]; c1.y = o2[1][1];
        *(ulonglong2*)ot               = c0;
        *(ulonglong2*)(ot + XS_STRIDE) = c1;
    }

    // ---- proj wide: out cols 0..127 ----
    #pragma unroll
    for (int p = 0; p < 3; p++) {
        float* dst = wb[0] + wkW[p] * 4 * BW_STRIDE + wnW[p];   // overlays Rs (dead)
        dst[0]             = wr[p].x;
        dst[BW_STRIDE]     = wr[p].y;
        dst[2 * BW_STRIDE] = wr[p].z;
        dst[3 * BW_STRIDE] = wr[p].w;
    }
    __syncthreads();   // tile 0 staged; attention reads of Ps/Rs done
    {
        u64 ap[2][8] = {};
        for (int t = 0; t < 8; t++) {
            if (t + 1 < 8) {
                const int nk = (t + 1) * KT;
                #pragma unroll
                for (int p = 0; p < 3; p++)
                    wr[p] = *(const float4*)(proj_w + wnW[p] * 192 + nk + wkW[p] * 4);
            }
            const float* bt = wb[t & 1];
            const float* xk = Xs + (t * KT) * XS_STRIDE;
            #pragma unroll 4
            for (int k = 0; k < KT; k++) {
                ulonglong2 a2 = *(const ulonglong2*)(xk + k * XS_STRIDE + i * 4);
                const float* br = bt + k * BW_STRIDE + j * 8;
                float4 b0 = *(const float4*)br;
                float4 b1 = *(const float4*)(br + 4);
                u64 q0 = bc2(b0.x), q1 = bc2(b0.y), q2 = bc2(b0.z), q3 = bc2(b0.w);
                fma2(ap[0][0], a2.x, q0); fma2(ap[1][0], a2.y, q0);
                fma2(ap[0][1], a2.x, q1); fma2(ap[1][1], a2.y, q1);
                fma2(ap[0][2], a2.x, q2); fma2(ap[1][2], a2.y, q2);
                fma2(ap[0][3], a2.x, q3); fma2(ap[1][3], a2.y, q3);
                u64 q4 = bc2(b1.x), q5 = bc2(b1.y), q6 = bc2(b1.z), q7 = bc2(b1.w);
                fma2(ap[0][4], a2.x, q4); fma2(ap[1][4], a2.y, q4);
                fma2(ap[0][5], a2.x, q5); fma2(ap[1][5], a2.y, q5);
                fma2(ap[0][6], a2.x, q6); fma2(ap[1][6], a2.y, q6);
                fma2(ap[0][7], a2.x, q7); fma2(ap[1][7], a2.y, q7);
            }
            if (t + 1 < 8) {
                float* bn = wb[(t + 1) & 1];
                #pragma unroll
                for (int p = 0; p < 3; p++) {
                    float* dst = bn + wkW[p] * 4 * BW_STRIDE + wnW[p];
                    dst[0]             = wr[p].x;
                    dst[BW_STRIDE]     = wr[p].y;
                    dst[2 * BW_STRIDE] = wr[p].z;
                    dst[3 * BW_STRIDE] = wr[p].w;
                }
                __syncthreads();
            }
        }
        const int n = j * 8;
        float4 pb0 = *(const float4*)(proj_b + n);
        float4 pb1 = *(const float4*)(proj_b + n + 4);
        float2 L[8], Hh[8];
        #pragma unroll
        for (int c = 0; c < 8; c++) { L[c] = unpk(ap[0][c]); Hh[c] = unpk(ap[1][c]); }
        const int m0 = i * 4;
        float* po0 = out + base + (((m0 + 0) >> 3) * 256 + ((m0 + 0) & 7)) * 192 + n;
        float* po1 = out + base + (((m0 + 1) >> 3) * 256 + ((m0 + 1) & 7)) * 192 + n;
        float* po2 = out + base + (((m0 + 2) >> 3) * 256 + ((m0 + 2) & 7)) * 192 + n;
        float* po3 = out + base + (((m0 + 3) >> 3) * 256 + ((m0 + 3) & 7)) * 192 + n;
        *(float4*)(po0)     = make_float4(L[0].x + pb0.x, L[1].x + pb0.y, L[2].x + pb0.z, L[3].x + pb0.w);
        *(float4*)(po0 + 4) = make_float4(L[4].x + pb1.x, L[5].x + pb1.y, L[6].x + pb1.z, L[7].x + pb1.w);
        *(float4*)(po1)     = make_float4(L[0].y + pb0.x, L[1].y + pb0.y, L[2].y + pb0.z, L[3].y + pb0.w);
        *(float4*)(po1 + 4) = make_float4(L[4].y + pb1.x, L[5].y + pb1.y, L[6].y + pb1.z, L[7].y + pb1.w);
        *(float4*)(po2)     = make_float4(Hh[0].x + pb0.x, Hh[1].x + pb0.y, Hh[2].x + pb0.z, Hh[3].x + pb0.w);
        *(float4*)(po2 + 4) = make_float4(Hh[4].x + pb1.x, Hh[5].x + pb1.y, Hh[6].x + pb1.z, Hh[7].x + pb1.w);
        *(float4*)(po3)     = make_float4(Hh[0].y + pb0.x, Hh[1].y + pb0.y, Hh[2].y + pb0.z, Hh[3].y + pb0.w);
        *(float4*)(po3 + 4) = make_float4(Hh[4].y + pb1.x, Hh[5].y + pb1.y, Hh[6].y + pb1.z, Hh[7].y + pb1.w);
    }

    // ---- proj narrow: out cols 128..191 ----
    wrN[0] = *(const float4*)(proj_w + (128 + wnN[0]) * 192 + wkN[0] * 4);
    if (tid < 128)
        wrN[1] = *(const float4*)(proj_w + (128 + wnN[1]) * 192 + wkN[1] * 4);
    {
        float* dst = wb[0] + wkN[0] * 4 * BN_STRIDE + wnN[0];   // buf0 free (last read t=6)
        dst[0] = wrN[0].x; dst[BN_STRIDE] = wrN[0].y;
        dst[2 * BN_STRIDE] = wrN[0].z; dst[3 * BN_STRIDE] = wrN[0].w;
        if (tid < 128) {
            float* d2 = wb[0] + wkN[1] * 4 * BN_STRIDE + wnN[1];
            d2[0] = wrN[1].x; d2[BN_STRIDE] = wrN[1].y;
            d2[2 * BN_STRIDE] = wrN[1].z; d2[3 * BN_STRIDE] = wrN[1].w;
        }
    }
    __syncthreads();
    {
        u64 an[2][4] = {};
        for (int t = 0; t < 8; t++) {
            if (t + 1 < 8) {
                const int nk = (t + 1) * KT;
                wrN[0] = *(const float4*)(proj_w + (128 + wnN[0]) * 192 + nk + wkN[0] * 4);
                if (tid < 128)
                    wrN[1] = *(const float4*)(proj_w + (128 + wnN[1]) * 192 + nk + wkN[1] * 4);
            }
            const float* bt = wb[t & 1];
            const float* xk = Xs + (t * KT) * XS_STRIDE;
            #pragma unroll 4
            for (int k = 0; k < KT; k++) {
                ulonglong2 a2 = *(const ulonglong2*)(xk + k * XS_STRIDE + i * 4);
                float4 b0 = *(const float4*)(bt + k * BN_STRIDE + j * 4);
                u64 q0 = bc2(b0.x), q1 = bc2(b0.y), q2 = bc2(b0.z), q3 = bc2(b0.w);
                fma2(an[0][0], a2.x, q0); fma2(an[1][0], a2.y, q0);
                fma2(an[0][1], a2.x, q1); fma2(an[1][1], a2.y, q1);
                fma2(an[0][2], a2.x, q2); fma2(an[1][2], a2.y, q2);
                fma2(an[0][3], a2.x, q3); fma2(an[1][3], a2.y, q3);
            }
            if (t + 1 < 8) {
                float* bn = wb[(t + 1) & 1];
                float* dst = bn + wkN[0] * 4 * BN_STRIDE + wnN[0];
                dst[0] = wrN[0].x; dst[BN_STRIDE] = wrN[0].y;
                dst[2 * BN_STRIDE] = wrN[0].z; dst[3 * BN_STRIDE] = wrN[0].w;
                if (tid < 128) {
                    float* d2 = bn + wkN[1] * 4 * BN_STRIDE + wnN[1];
                    d2[0] = wrN[1].x; d2[BN_STRIDE] = wrN[1].y;
                    d2[2 * BN_STRIDE] = wrN[1].z; d2[3 * BN_STRIDE] = wrN[1].w;
                }
                __syncthreads();
            }
        }
        const int n = 128 + j * 4;
        float4 pb = *(const float4*)(proj_b + n);
        float2 L[4], Hh[4];
        #pragma unroll
        for (int c = 0; c < 4; c++) { L[c] = unpk(an[0][c]); Hh[c] = unpk(an[1][c]); }
        const int m0 = i * 4;
        float* po0 = out + base + (((m0 + 0) >> 3) * 256 + ((m0 + 0) & 7)) * 192 + n;
        float* po1 = out + base + (((m0 + 1) >> 3) * 256 + ((m0 + 1) & 7)) * 192 + n;
        float* po2 = out + base + (((m0 + 2) >> 3) * 256 + ((m0 + 2) & 7)) * 192 + n;
        float* po3 = out + base + (((m0 + 3) >> 3) * 256 + ((m0 + 3) & 7)) * 192 + n;
        *(float4*)po0 = make_float4(L[0].x + pb.x, L[1].x + pb.y, L[2].x + pb.z, L[3].x + pb.w);
        *(float4*)po1 = make_float4(L[0].y + pb.x, L[1].y + pb.y, L[2].y + pb.z, L[3].y + pb.w);
        *(float4*)po2 = make_float4(Hh[0].x + pb.x, Hh[1].x + pb.y, Hh[2].x + pb.z, Hh[3].x + pb.w);
        *(float4*)po3 = make_float4(Hh[0].y + pb.x, Hh[1].y + pb.y, Hh[2].y + pb.z, Hh[3].y + pb.w);
    }
}

extern "C" void kernel_launch(void* const* d_in, const int* in_sizes, int n_in,
                              void* d_out, int out_size) {
    (void)in_sizes; (void)n_in; (void)out_size;
    cudaFuncSetAttribute(win_attn_kernel,
                         cudaFuncAttributeMaxDynamicSharedMemorySize, SMEM_BYTES);
    win_attn_kernel<<<4096, 256, SMEM_BYTES>>>(
        (const float*)d_in[0],   // x
        (const float*)d_in[1],   // qkv_w
        (const float*)d_in[2],   // proj_w
        (const float*)d_in[3],   // proj_b
        (const float*)d_in[4],   // rpb_table
        (float*)d_out);
}

// round 11
// speedup vs baseline: 1.2706x; 1.2706x over previous
#include <cuda_runtime.h>

// Fused Swin window attention, fp32 + packed f32x2 FMA. One CTA per 8x8 window.
// B=4, H=W=256, C=192, WS=8, NH=6, HD=32.
// R8: 8m x 6n weight-GEMM thread tiles, uniform 192-col chunks (Q|K|V|proj),
// KT=16 double-buffered one-barrier pipeline, conflict-aware transpose,
// rpb overlay, Ps-aliased weight buffer.
//
// smem (floats):
//   Xs [192][68]  X^T (k-major, padded); reused as attn-out^T for proj
//   Qs [6][32][64], Ks [6][32][64]  d-major
//   Vs [6][64][32] token-major
//   Ps [64][68]   softmax probs (attention) / weight buf1 (GEMMs, 16x196)
//   Bt [16][196]  weight buf0 (GEMMs) / rpb table (attention)

#define XST 68
#define PST 68
#define BST 196
#define KT  16

#define SM_X 0
#define SM_Q 13056
#define SM_K 25344
#define SM_V 37632
#define SM_P 49920
#define SM_B 54272
#define SM_FLOATS 57472
#define SMEM_BYTES (SM_FLOATS * 4)

typedef unsigned long long u64;

__device__ __forceinline__ u64 bc2(float v) {
    u64 r;
    asm("mov.b64 %0, {%1, %1};" : "=l"(r) : "r"(__float_as_uint(v)));
    return r;
}
__device__ __forceinline__ void fma2(u64& d, u64 a, u64 b) {
    asm("fma.rn.f32x2 %0, %1, %2, %0;" : "+l"(d) : "l"(a), "l"(b));
}
__device__ __forceinline__ u64 mul2(u64 a, u64 b) {
    u64 r;
    asm("mul.rn.f32x2 %0, %1, %2;" : "=l"(r) : "l"(a), "l"(b));
    return r;
}
__device__ __forceinline__ float2 unpk(u64 a) {
    unsigned lo, hi;
    asm("mov.b64 {%0, %1}, %2;" : "=r"(lo), "=r"(hi) : "l"(a));
    return make_float2(__uint_as_float(lo), __uint_as_float(hi));
}

__global__ __launch_bounds__(256, 1)
void win_attn_kernel(const float* __restrict__ x,
                     const float* __restrict__ qkv_w,
                     const float* __restrict__ proj_w,
                     const float* __restrict__ proj_b,
                     const float* __restrict__ rpb,
                     float* __restrict__ out)
{
    extern __shared__ float sm[];
    float* Xs = sm + SM_X;
    float* Qs = sm + SM_Q;
    float* Ks = sm + SM_K;
    float* Vs = sm + SM_V;
    float* Ps = sm + SM_P;
    float* Rs = sm + SM_B;       // rpb table, attention phase only
    float* wb[2];
    wb[0] = sm + SM_B;           // weight buf0 (GEMM phases)
    wb[1] = sm + SM_P;           // weight buf1 aliases Ps

    const int tid  = threadIdx.x;
    const int lane = tid & 31;
    const int w    = tid >> 5;
    // weight-GEMM thread tile: rows mg*8..mg*8+7, cols colT..colT+5
    const int mg   = lane >> 2;
    const int ls   = lane & 3;
    const int colT = w * 24 + ls * 6;
    // attention mapping (4m x 4n)
    const int i = tid >> 4;
    const int j = tid & 15;

    const int blk = blockIdx.x;
    const int b  = blk >> 10;
    const int wy = (blk >> 5) & 31;
    const int wx = blk & 31;
    const int base = ((b * 256 + wy * 8) * 256 + wx * 8) * 192;

    // ---- load X window transposed into Xs[k][m] (conflict-aware mapping) ----
    {
        const int dm = (tid >> 2) & 7;
        const int dc = tid & 3;
        const int wv = tid >> 5;
        const int m  = wv * 8 + dm;
        const float* src = x + base + (wv * 256 + dm) * 192 + dc * 4;
        float* dstb = Xs + dc * 4 * XST + m;
        #pragma unroll
        for (int p = 0; p < 12; p++) {
            float4 v = *(const float4*)(src + p * 16);
            float* dst = dstb + p * 16 * XST;
            dst[0]       = v.x;
            dst[XST]     = v.y;
            dst[2 * XST] = v.z;
            dst[3 * XST] = v.w;
        }
    }

    const u64 sc2 = bc2(0.17677669529663687f);  // 32^-0.5 packed

    // staging coords: tile = 16k x 192n = 768 float4; 3 per thread.
    // idx -> col = idx>>2 (0..191), k-row base = (idx&3)*4
    int wc[3], wk[3];
    #pragma unroll
    for (int p = 0; p < 3; p++) {
        int idx = p * 256 + tid;
        wc[p] = idx >> 2;
        wk[p] = (idx & 3) * 4;
    }

    float4 wr[3];
    // prologue: QKV chunk 0 (Q), tile 0
    #pragma unroll
    for (int p = 0; p < 3; p++)
        wr[p] = *(const float4*)(qkv_w + wc[p] * 192 + wk[p]);
    #pragma unroll
    for (int p = 0; p < 3; p++) {
        float* dst = wb[0] + wk[p] * BST + wc[p];
        dst[0]       = wr[p].x;
        dst[BST]     = wr[p].y;
        dst[2 * BST] = wr[p].z;
        dst[3 * BST] = wr[p].w;
    }
    __syncthreads();   // tile 0 staged; also orders Xs stores

    // ---- GEMM1: QKV = X @ qkv_w^T; 3 chunks (Q,K,V) x 12 K-tiles ----
    u64 acc[4][6] = {};
    for (int t = 0; t < 36; t++) {
        const int q = t % 12;
        if (t + 1 < 36) {
            const int nn = ((t + 1) / 12) * 192;
            const int nk = ((t + 1) % 12) * KT;
            #pragma unroll
            for (int p = 0; p < 3; p++)
                wr[p] = *(const float4*)(qkv_w + (nn + wc[p]) * 192 + nk + wk[p]);
        }
        const float* bt = wb[t & 1];
        const float* xk = Xs + (q * KT) * XST;
        #pragma unroll 4
        for (int k = 0; k < KT; k++) {
            ulonglong2 aLo = *(const ulonglong2*)(xk + k * XST + mg * 8);
            ulonglong2 aHi = *(const ulonglong2*)(xk + k * XST + mg * 8 + 4);
            const float* br = bt + k * BST + colT;
            float2 b01 = *(const float2*)br;
            float2 b23 = *(const float2*)(br + 2);
            float2 b45 = *(const float2*)(br + 4);
            u64 B0 = bc2(b01.x), B1 = bc2(b01.y), B2 = bc2(b23.x);
            u64 B3 = bc2(b23.y), B4 = bc2(b45.x), B5 = bc2(b45.y);
            fma2(acc[0][0], aLo.x, B0); fma2(acc[1][0], aLo.y, B0);
            fma2(acc[2][0], aHi.x, B0); fma2(acc[3][0], aHi.y, B0);
            fma2(acc[0][1], aLo.x, B1); fma2(acc[1][1], aLo.y, B1);
            fma2(acc[2][1], aHi.x, B1); fma2(acc[3][1], aHi.y, B1);
            fma2(acc[0][2], aLo.x, B2); fma2(acc[1][2], aLo.y, B2);
            fma2(acc[2][2], aHi.x, B2); fma2(acc[3][2], aHi.y, B2);
            fma2(acc[0][3], aLo.x, B3); fma2(acc[1][3], aLo.y, B3);
            fma2(acc[2][3], aHi.x, B3); fma2(acc[3][3], aHi.y, B3);
            fma2(acc[0][4], aLo.x, B4); fma2(acc[1][4], aLo.y, B4);
            fma2(acc[2][4], aHi.x, B4); fma2(acc[3][4], aHi.y, B4);
            fma2(acc[0][5], aLo.x, B5); fma2(acc[1][5], aLo.y, B5);
            fma2(acc[2][5], aHi.x, B5); fma2(acc[3][5], aHi.y, B5);
        }
        if (t + 1 < 36) {
            float* bn = wb[(t + 1) & 1];
            #pragma unroll
            for (int p = 0; p < 3; p++) {
                float* dst = bn + wk[p] * BST + wc[p];
                dst[0]       = wr[p].x;
                dst[BST]     = wr[p].y;
                dst[2 * BST] = wr[p].z;
                dst[3 * BST] = wr[p].w;
            }
        }
        if (q == 11) {
            const int ch = t / 12;       // 0=Q 1=K 2=V
            if (ch == 0) {
                #pragma unroll
                for (int c = 0; c < 6; c++) {
                    const int col = colT + c;
                    float* qp = Qs + (col >> 5) * 2048 + (col & 31) * 64 + mg * 8;
                    ulonglong2 lo, hi;
                    lo.x = mul2(acc[0][c], sc2); lo.y = mul2(acc[1][c], sc2);
                    hi.x = mul2(acc[2][c], sc2); hi.y = mul2(acc[3][c], sc2);
                    *(ulonglong2*)qp       = lo;
                    *(ulonglong2*)(qp + 4) = hi;
                }
            } else if (ch == 1) {
                #pragma unroll
                for (int c = 0; c < 6; c++) {
                    const int col = colT + c;
                    float* kp = Ks + (col >> 5) * 2048 + (col & 31) * 64 + mg * 8;
                    ulonglong2 lo, hi;
                    lo.x = acc[0][c]; lo.y = acc[1][c];
                    hi.x = acc[2][c]; hi.y = acc[3][c];
                    *(ulonglong2*)kp       = lo;
                    *(ulonglong2*)(kp + 4) = hi;
                }
            } else {
                #pragma unroll
                for (int c = 0; c < 6; c++) {
                    const int col = colT + c;
                    float* vp = Vs + (col >> 5) * 2048 + (col & 31);
                    #pragma unroll
                    for (int mp = 0; mp < 4; mp++) {
                        float2 f = unpk(acc[mp][c]);
                        vp[(mg * 8 + 2 * mp) * 32]     = f.x;
                        vp[(mg * 8 + 2 * mp + 1) * 32] = f.y;
                    }
                }
            }
            #pragma unroll
            for (int mp = 0; mp < 4; mp++)
                #pragma unroll
                for (int c = 0; c < 6; c++) acc[mp][c] = 0ull;
        }
        __syncthreads();
    }

    // ---- stage rpb into Rs (overlays wb0; all wb0 reads done) + proj prefetch ----
    for (int t = tid; t < 1350; t += 256) Rs[t] = rpb[t];
    #pragma unroll
    for (int p = 0; p < 3; p++)
        wr[p] = *(const float4*)(proj_w + wc[p] * 192 + wk[p]);
    __syncthreads();   // Rs ready (Q/K/V already fenced by loop-final barrier)

    // ---- rpb offsets for this thread's S tile ----
    int ridx[4][4];
    #pragma unroll
    for (int di = 0; di < 4; di++) {
        int m = i * 4 + di, qr = m >> 3, qc = m & 7;
        #pragma unroll
        for (int dj = 0; dj < 4; dj++) {
            int n = j * 4 + dj, kr = n >> 3, kc = n & 7;
            ridx[di][dj] = ((qr - kr + 7) * 15 + (qc - kc + 7)) * 6;
        }
    }

    // ---- attention per head ----
    for (int h = 0; h < 6; h++) {
        const float* qh = Qs + h * 2048;
        const float* kh = Ks + h * 2048;
        u64 s2[4][2] = {};
        #pragma unroll 4
        for (int d = 0; d < 32; d++) {
            float4 a      = *(const float4*)(qh + d * 64 + i * 4);
            ulonglong2 b2 = *(const ulonglong2*)(kh + d * 64 + j * 4);
            u64 a0 = bc2(a.x), a1 = bc2(a.y), a2b = bc2(a.z), a3 = bc2(a.w);
            fma2(s2[0][0], a0, b2.x);  fma2(s2[0][1], a0, b2.y);
            fma2(s2[1][0], a1, b2.x);  fma2(s2[1][1], a1, b2.y);
            fma2(s2[2][0], a2b, b2.x); fma2(s2[2][1], a2b, b2.y);
            fma2(s2[3][0], a3, b2.x);  fma2(s2[3][1], a3, b2.y);
        }
        float p[4][4];
        #pragma unroll
        for (int di = 0; di < 4; di++) {
            float2 s01 = unpk(s2[di][0]), s23 = unpk(s2[di][1]);
            float sv0 = s01.x + Rs[ridx[di][0] + h];
            float sv1 = s01.y + Rs[ridx[di][1] + h];
            float sv2 = s23.x + Rs[ridx[di][2] + h];
            float sv3 = s23.y + Rs[ridx[di][3] + h];
            float mx = fmaxf(fmaxf(sv0, sv1), fmaxf(sv2, sv3));
            mx = fmaxf(mx, __shfl_xor_sync(0xffffffffu, mx, 8));
            mx = fmaxf(mx, __shfl_xor_sync(0xffffffffu, mx, 4));
            mx = fmaxf(mx, __shfl_xor_sync(0xffffffffu, mx, 2));
            mx = fmaxf(mx, __shfl_xor_sync(0xffffffffu, mx, 1));
            float e0 = __expf(sv0 - mx), e1 = __expf(sv1 - mx);
            float e2 = __expf(sv2 - mx), e3 = __expf(sv3 - mx);
            float sum = (e0 + e1) + (e2 + e3);
            sum += __shfl_xor_sync(0xffffffffu, sum, 8);
            sum += __shfl_xor_sync(0xffffffffu, sum, 4);
            sum += __shfl_xor_sync(0xffffffffu, sum, 2);
            sum += __shfl_xor_sync(0xffffffffu, sum, 1);
            float inv = __frcp_rn(sum);
            p[di][0] = e0 * inv; p[di][1] = e1 * inv;
            p[di][2] = e2 * inv; p[di][3] = e3 * inv;
        }
        __syncthreads();   // prior Ps readers done
        #pragma unroll
        for (int dj = 0; dj < 4; dj++)
            *(float4*)(Ps + (j * 4 + dj) * PST + i * 4) =
                make_float4(p[0][dj], p[1][dj], p[2][dj], p[3][dj]);
        __syncthreads();   // Ps ready

        const float* vh = Vs + h * 2048;
        u64 o2[2][2] = {};
        #pragma unroll 4
        for (int kk = 0; kk < 64; kk++) {
            ulonglong2 a2 = *(const ulonglong2*)(Ps + kk * PST + i * 4);
            float2 bv = *(const float2*)(vh + kk * 32 + j * 2);
            u64 b0 = bc2(bv.x), b1 = bc2(bv.y);
            fma2(o2[0][0], a2.x, b0); fma2(o2[0][1], a2.x, b1);
            fma2(o2[1][0], a2.y, b0); fma2(o2[1][1], a2.y, b1);
        }
        float* ot = Xs + (h * 32 + j * 2) * XST + i * 4;
        ulonglong2 c0, c1;
        c0.x = o2[0][0]; c0.y = o2[1][0];
        c1.x = o2[0][1]; c1.y = o2[1][1];
        *(ulonglong2*)ot         = c0;
        *(ulonglong2*)(ot + XST) = c1;
    }

    // ---- proj: out = O @ proj_w^T + b; one 192-col chunk x 12 K-tiles ----
    #pragma unroll
    for (int p = 0; p < 3; p++) {
        float* dst = wb[0] + wk[p] * BST + wc[p];   // overlays Rs (dead)
        dst[0]       = wr[p].x;
        dst[BST]     = wr[p].y;
        dst[2 * BST] = wr[p].z;
        dst[3 * BST] = wr[p].w;
    }
    __syncthreads();   // tile 0 staged; attention Ps/Rs reads + Xs writes done
    for (int t = 0; t < 12; t++) {
        if (t + 1 < 12) {
            const int nk = (t + 1) * KT;
            #pragma unroll
            for (int p = 0; p < 3; p++)
                wr[p] = *(const float4*)(proj_w + wc[p] * 192 + nk + wk[p]);
        }
        const float* bt = wb[t & 1];
        const float* xk = Xs + (t * KT) * XST;
        #pragma unroll 4
        for (int k = 0; k < KT; k++) {
            ulonglong2 aLo = *(const ulonglong2*)(xk + k * XST + mg * 8);
            ulonglong2 aHi = *(const ulonglong2*)(xk + k * XST + mg * 8 + 4);
            const float* br = bt + k * BST + colT;
            float2 b01 = *(const float2*)br;
            float2 b23 = *(const float2*)(br + 2);
            float2 b45 = *(const float2*)(br + 4);
            u64 B0 = bc2(b01.x), B1 = bc2(b01.y), B2 = bc2(b23.x);
            u64 B3 = bc2(b23.y), B4 = bc2(b45.x), B5 = bc2(b45.y);
            fma2(acc[0][0], aLo.x, B0); fma2(acc[1][0], aLo.y, B0);
            fma2(acc[2][0], aHi.x, B0); fma2(acc[3][0], aHi.y, B0);
            fma2(acc[0][1], aLo.x, B1); fma2(acc[1][1], aLo.y, B1);
            fma2(acc[2][1], aHi.x, B1); fma2(acc[3][1], aHi.y, B1);
            fma2(acc[0][2], aLo.x, B2); fma2(acc[1][2], aLo.y, B2);
            fma2(acc[2][2], aHi.x, B2); fma2(acc[3][2], aHi.y, B2);
            fma2(acc[0][3], aLo.x, B3); fma2(acc[1][3], aLo.y, B3);
            fma2(acc[2][3], aHi.x, B3); fma2(acc[3][3], aHi.y, B3);
            fma2(acc[0][4], aLo.x, B4); fma2(acc[1][4], aLo.y, B4);
            fma2(acc[2][4], aHi.x, B4); fma2(acc[3][4], aHi.y, B4);
            fma2(acc[0][5], aLo.x, B5); fma2(acc[1][5], aLo.y, B5);
            fma2(acc[2][5], aHi.x, B5); fma2(acc[3][5], aHi.y, B5);
        }
        if (t + 1 < 12) {
            float* bn = wb[(t + 1) & 1];
            #pragma unroll
            for (int p = 0; p < 3; p++) {
                float* dst = bn + wk[p] * BST + wc[p];
                dst[0]       = wr[p].x;
                dst[BST]     = wr[p].y;
                dst[2 * BST] = wr[p].z;
                dst[3 * BST] = wr[p].w;
            }
            __syncthreads();
        }
    }
    // proj epilogue: rows mg*8..+7, cols colT..colT+5
    {
        float2 pb01 = *(const float2*)(proj_b + colT);
        float2 pb23 = *(const float2*)(proj_b + colT + 2);
        float2 pb45 = *(const float2*)(proj_b + colT + 4);
        #pragma unroll
        for (int mp = 0; mp < 4; mp++) {
            float2 f[6];
            #pragma unroll
            for (int c = 0; c < 6; c++) f[c] = unpk(acc[mp][c]);
            const int m = mg * 8 + 2 * mp;
            float* po = out + base + ((m >> 3) * 256 + (m & 7)) * 192 + colT;
            *(float2*)(po)     = make_float2(f[0].x + pb01.x, f[1].x + pb01.y);
            *(float2*)(po + 2) = make_float2(f[2].x + pb23.x, f[3].x + pb23.y);
            *(float2*)(po + 4) = make_float2(f[4].x + pb45.x, f[5].x + pb45.y);
            float* po2 = po + 192;   // row m+1 (same 8-block)
            *(float2*)(po2)     = make_float2(f[0].y + pb01.x, f[1].y + pb01.y);
            *(float2*)(po2 + 2) = make_float2(f[2].y + pb23.x, f[3].y + pb23.y);
            *(float2*)(po2 + 4) = make_float2(f[4].y + pb45.x, f[5].y + pb45.y);
        }
    }
}

extern "C" void kernel_launch(void* const* d_in, const int* in_sizes, int n_in,
                              void* d_out, int out_size) {
    (void)in_sizes; (void)n_in; (void)out_size;
    cudaFuncSetAttribute(win_attn_kernel,
                         cudaFuncAttributeMaxDynamicSharedMemorySize, SMEM_BYTES);
    win_attn_kernel<<<4096, 256, SMEM_BYTES>>>(
        (const float*)d_in[0],   // x
        (const float*)d_in[1],   // qkv_w
        (const float*)d_in[2],   // proj_w
        (const float*)d_in[3],   // proj_b
        (const float*)d_in[4],   // rpb_table
        (float*)d_out);
}